// round 2
// baseline (speedup 1.0000x reference)
#include <cuda_runtime.h>

#define NS   64
#define PP   4096
#define BBAT 8
#define HH   32
#define EE   34
#define NTOK (BBAT*PP)        /* 32768 rows per step */
#define NHID (NTOK*HH)        /* 1048576 floats per step */
#define QSTR 36               /* padded stride for q rows (16B aligned) */
#define KVSTR 72              /* padded stride for k+v per token */

// Scratch: q / (k,v) per token, 10 slots for the batched obs phase (pred reuses slot 0).
__device__ __align__(16) float g_Q [10*NTOK*QSTR];
__device__ __align__(16) float g_KV[10*NTOK*KVSTR];

// ---------------------------------------------------------------------------
// Kernel A: per-token QKV projection.
// token vector = [h(32) , row/64 , col/64] (E=34); outputs q(34), k(34), v(34).
// One thread per token; weights staged in smem with stride-36 rows (16B aligned).
// ---------------------------------------------------------------------------
__global__ void __launch_bounds__(256)
qkv_kernel(const float* __restrict__ h,
           const float* __restrict__ ipw, const float* __restrict__ ipb)
{
    __shared__ __align__(16) float sw[102*36];
    __shared__ float sb[102];
    int tid = threadIdx.x;
    for (int i = tid; i < 102*34; i += 256) {
        int ri = i / 34, ci = i - ri*34;
        sw[ri*36 + ci] = ipw[i];
    }
    if (tid < 102) sb[tid] = ipb[tid];
    __syncthreads();

    int tok = blockIdx.x * 256 + tid;
    int t = tok >> 15;             // step slot (obs: 0..9, pred: 0)
    int n = tok & (NTOK - 1);
    int p = n & (PP - 1);

    const float4* hr4 = (const float4*)(h + (size_t)t*NHID + (size_t)n*HH);
    float xv[EE];
#pragma unroll
    for (int e4 = 0; e4 < 8; e4++) {
        float4 v = hr4[e4];
        xv[e4*4+0] = v.x; xv[e4*4+1] = v.y; xv[e4*4+2] = v.z; xv[e4*4+3] = v.w;
    }
    int r = p >> 6, c = p & 63;
    xv[32] = (float)r * (1.0f/64.0f);
    xv[33] = (float)c * (1.0f/64.0f);

    float* q  = g_Q  + (size_t)tok*QSTR;
    float* kv = g_KV + (size_t)tok*KVSTR;

#pragma unroll 2
    for (int i = 0; i < 34; i++) {
        float a = sb[i];
#pragma unroll
        for (int e = 0; e < EE; e++) a = fmaf(sw[i*36+e], xv[e], a);
        q[i] = a;
    }
#pragma unroll 2
    for (int i = 0; i < 34; i++) {
        float a = sb[34+i];
#pragma unroll
        for (int e = 0; e < EE; e++) a = fmaf(sw[(34+i)*36+e], xv[e], a);
        kv[i] = a;
    }
#pragma unroll 2
    for (int i = 0; i < 34; i++) {
        float a = sb[68+i];
#pragma unroll
        for (int e = 0; e < EE; e++) a = fmaf(sw[(68+i)*36+e], xv[e], a);
        kv[36+i] = a;
    }
}

// ---------------------------------------------------------------------------
// Kernel B: per-center fused attention epilogue.
// scores(center q vs 9 neighbor k) -> softmax -> av -> out_proj -> fc_sa
// -> +residual -> fc2 -> layernorm -> output row.
// One thread per center row; everything register-resident, weights in smem.
// smem layout (floats): opw@0(34x36) opb@1224 saw@1260(32x36) sab@2412
//                       f2w@2444(32x32) f2b@3468 lng@3500 lnb@3532
// ---------------------------------------------------------------------------
__global__ void __launch_bounds__(256)
attn_kernel(const float* __restrict__ h,
            const float* __restrict__ opw, const float* __restrict__ opb,
            const float* __restrict__ saw, const float* __restrict__ sab,
            const float* __restrict__ f2w, const float* __restrict__ f2b,
            const float* __restrict__ lng, const float* __restrict__ lnb,
            float* __restrict__ outp)
{
    __shared__ __align__(16) float sm[3564];
    int tid = threadIdx.x;
    for (int i = tid; i < 34*34; i += 256) { int ri=i/34; sm[ri*36 + (i-ri*34)] = opw[i]; }
    for (int i = tid; i < 32*34; i += 256) { int ri=i/34; sm[1260 + ri*36 + (i-ri*34)] = saw[i]; }
    for (int i = tid; i < 1024;  i += 256) sm[2444+i] = f2w[i];
    if (tid < 34)  sm[1224+tid] = opb[tid];
    if (tid < 32)  sm[2412+tid] = sab[tid];
    if (tid < 32)  sm[3468+tid] = f2b[tid];
    if (tid < 32)  sm[3500+tid] = lng[tid];
    if (tid < 32)  sm[3532+tid] = lnb[tid];
    __syncthreads();

    int g = blockIdx.x * 256 + tid;
    int t = g >> 15;
    int n = g & (NTOK - 1);
    int p = n & (PP - 1);
    int b = n >> 12;
    int r = p >> 6, c = p & 63;
    // boundary-corrected neighborhood center (shift, not clamp)
    int rr = r + (r == 0) - (r == 63);
    int cc = c + (c == 0) - (c == 63);
    int base = t*NTOK + b*PP;

    // query = q of token NEIGH[p][4] (the *shifted* center)
    const float4* qp4 = (const float4*)(g_Q + (size_t)(base + rr*NS + cc)*QSTR);
    float q[36];
#pragma unroll
    for (int e4 = 0; e4 < 9; e4++) {
        float4 v = qp4[e4];
        q[e4*4+0] = v.x; q[e4*4+1] = v.y; q[e4*4+2] = v.z; q[e4*4+3] = v.w;
    }

    float s[9];
#pragma unroll
    for (int dy = 0; dy < 3; dy++)
#pragma unroll
    for (int dx = 0; dx < 3; dx++) {
        int np = (rr + dy - 1)*NS + (cc + dx - 1);
        const float4* kp4 = (const float4*)(g_KV + (size_t)(base + np)*KVSTR);
        float a = 0.f;
#pragma unroll
        for (int e4 = 0; e4 < 9; e4++) {           // 36 floats; [34],[35] are garbage
            float4 kvv = kp4[e4];
            if (e4 < 8) {
                a = fmaf(q[e4*4+0], kvv.x, a);
                a = fmaf(q[e4*4+1], kvv.y, a);
                a = fmaf(q[e4*4+2], kvv.z, a);
                a = fmaf(q[e4*4+3], kvv.w, a);
            } else {
                a = fmaf(q[32], kvv.x, a);
                a = fmaf(q[33], kvv.y, a);
            }
        }
        s[dy*3+dx] = a * 0.17149858514250882f;     // 1/sqrt(34)
    }

    float mx = s[0];
#pragma unroll
    for (int i = 1; i < 9; i++) mx = fmaxf(mx, s[i]);
    float sum = 0.f;
#pragma unroll
    for (int i = 0; i < 9; i++) { s[i] = __expf(s[i] - mx); sum += s[i]; }
    float inv = __fdividef(1.0f, sum);

    float av[EE];
#pragma unroll
    for (int e = 0; e < EE; e++) av[e] = 0.f;
#pragma unroll
    for (int dy = 0; dy < 3; dy++)
#pragma unroll
    for (int dx = 0; dx < 3; dx++) {
        int np = (rr + dy - 1)*NS + (cc + dx - 1);
        const float4* vp4 = (const float4*)(g_KV + (size_t)(base + np)*KVSTR + 36);
        float w = s[dy*3+dx] * inv;
#pragma unroll
        for (int e4 = 0; e4 < 9; e4++) {
            float4 vv = vp4[e4];
            if (e4 < 8) {
                av[e4*4+0] = fmaf(w, vv.x, av[e4*4+0]);
                av[e4*4+1] = fmaf(w, vv.y, av[e4*4+1]);
                av[e4*4+2] = fmaf(w, vv.z, av[e4*4+2]);
                av[e4*4+3] = fmaf(w, vv.w, av[e4*4+3]);
            } else {
                av[32] = fmaf(w, vv.x, av[32]);
                av[33] = fmaf(w, vv.y, av[33]);
            }
        }
    }

    // out_proj (E x E)
    float o[EE];
#pragma unroll
    for (int i = 0; i < EE; i++) {
        float a = sm[1224+i];
#pragma unroll
        for (int e = 0; e < EE; e++) a = fmaf(sm[i*36+e], av[e], a);
        o[i] = a;
    }

    // fc_sa (H x E) + residual
    const float4* hr4 = (const float4*)(h + (size_t)t*NHID + (size_t)n*HH);
    float hr[HH];
#pragma unroll
    for (int e4 = 0; e4 < 8; e4++) {
        float4 v = hr4[e4];
        hr[e4*4+0] = v.x; hr[e4*4+1] = v.y; hr[e4*4+2] = v.z; hr[e4*4+3] = v.w;
    }
    float nh[HH];
#pragma unroll
    for (int i = 0; i < HH; i++) {
        float a = sm[2412+i];
#pragma unroll
        for (int e = 0; e < EE; e++) a = fmaf(sm[1260 + i*36 + e], o[e], a);
        nh[i] = hr[i] + a;
    }

    // fc2 (H x H)
    float y[HH];
    float mean = 0.f;
#pragma unroll
    for (int i = 0; i < HH; i++) {
        float a = sm[3468+i];
#pragma unroll
        for (int j = 0; j < HH; j++) a = fmaf(sm[2444 + i*32 + j], nh[j], a);
        y[i] = a; mean += a;
    }
    mean *= (1.0f/32.0f);
    float var = 0.f;
#pragma unroll
    for (int i = 0; i < HH; i++) { float d = y[i] - mean; var = fmaf(d, d, var); }
    var *= (1.0f/32.0f);
    float rinv = rsqrtf(var + 1e-5f);

    float4* orow4 = (float4*)(outp + (size_t)g*HH);
#pragma unroll
    for (int i4 = 0; i4 < 8; i4++) {
        float4 v;
        v.x = (y[i4*4+0] - mean)*rinv*sm[3500+i4*4+0] + sm[3532+i4*4+0];
        v.y = (y[i4*4+1] - mean)*rinv*sm[3500+i4*4+1] + sm[3532+i4*4+1];
        v.z = (y[i4*4+2] - mean)*rinv*sm[3500+i4*4+2] + sm[3532+i4*4+2];
        v.w = (y[i4*4+3] - mean)*rinv*sm[3500+i4*4+3] + sm[3532+i4*4+3];
        orow4[i4] = v;
    }
}

// ---------------------------------------------------------------------------
extern "C" void kernel_launch(void* const* d_in, const int* in_sizes, int n_in,
                              void* d_out, int out_size)
{
    const float* x   = (const float*)d_in[0];
    const float* ipw = (const float*)d_in[1];
    const float* ipb = (const float*)d_in[2];
    const float* opw = (const float*)d_in[3];
    const float* opb = (const float*)d_in[4];
    const float* saw = (const float*)d_in[5];
    const float* sab = (const float*)d_in[6];
    const float* f2w = (const float*)d_in[7];
    const float* f2b = (const float*)d_in[8];
    const float* lng = (const float*)d_in[9];
    const float* lnb = (const float*)d_in[10];
    float* out = (float*)d_out;

    // Observation phase: 10 independent steps, batched into one A+B pair.
    qkv_kernel <<<(10*NTOK)/256, 256>>>(x, ipw, ipb);
    attn_kernel<<<(10*NTOK)/256, 256>>>(x, opw, opb, saw, sab, f2w, f2b,
                                        lng, lnb, out);

    // Prediction phase: 50 sequential steps rolling on the previous output.
    for (int s = 0; s < 50; s++) {
        const float* hin = out + (size_t)(9 + s)*NHID;
        float* outstep   = out + (size_t)(10 + s)*NHID;
        qkv_kernel <<<NTOK/256, 256>>>(hin, ipw, ipb);
        attn_kernel<<<NTOK/256, 256>>>(hin, opw, opb, saw, sab, f2w, f2b,
                                       lng, lnb, outstep);
    }
}